// round 1
// baseline (speedup 1.0000x reference)
#include <cuda_runtime.h>

#define N_USERS 100000
#define N_ITEMS 50000
#define NNZ     1600000
#define DIM     64

// Scratch for the projected features (device globals: no allocation allowed).
__device__ float g_xw_user[N_USERS * DIM];
__device__ float g_xw_item[N_ITEMS * DIM];

// ---------------------------------------------------------------------------
// Dense projection: out[m, :] = x[m, :] @ W   (W is DIM x DIM, row-major)
// 256 threads/block = 4 rows x 64 cols. W staged in shared.
// ---------------------------------------------------------------------------
__global__ void gemm64_kernel(const float* __restrict__ x,
                              const float* __restrict__ W,
                              float* __restrict__ out, int M) {
    __shared__ float sW[DIM * DIM];
    int tid = threadIdx.x;
    #pragma unroll
    for (int i = 0; i < (DIM * DIM) / 256; i++)
        sW[tid + i * 256] = W[tid + i * 256];
    __syncthreads();

    int row = blockIdx.x * 4 + (tid >> 6);
    int col = tid & 63;
    if (row >= M) return;

    const float* xr = x + row * DIM;
    float acc = 0.0f;
    #pragma unroll
    for (int k = 0; k < DIM; k++)
        acc = fmaf(xr[k], sW[k * DIM + col], acc);
    out[row * DIM + col] = acc;
}

// ---------------------------------------------------------------------------
// Zero-fill the (poisoned) output buffer.
// ---------------------------------------------------------------------------
__global__ void zero_kernel(float4* __restrict__ out, int n4) {
    int i = blockIdx.x * blockDim.x + threadIdx.x;
    if (i < n4) out[i] = make_float4(0.f, 0.f, 0.f, 0.f);
}

// ---------------------------------------------------------------------------
// Fused bidirectional scatter:
//   out_user[r] += v * xw_item[c]     (ui_graph @ xw_item)
//   out_item[c] += v * xw_user[r]     (ui_graph^T @ xw_user)
// 16 threads per edge; thread g handles dims [4g, 4g+4).
// Threads 0..15 of an edge read consecutive float4s -> coalesced 256B row.
// ---------------------------------------------------------------------------
__global__ void scatter_kernel(const int*   __restrict__ rows,
                               const int*   __restrict__ cols,
                               const float* __restrict__ vals,
                               float* __restrict__ out_user,
                               float* __restrict__ out_item) {
    long long t = (long long)blockIdx.x * blockDim.x + threadIdx.x;
    int e = (int)(t >> 4);
    int g = (int)(t & 15);
    if (e >= NNZ) return;

    int   r = rows[e];
    int   c = cols[e];
    float v = vals[e];

    // user <- item direction
    float4 xi = *reinterpret_cast<const float4*>(&g_xw_item[c * DIM + g * 4]);
    float* du = &out_user[r * DIM + g * 4];
    atomicAdd(du + 0, v * xi.x);
    atomicAdd(du + 1, v * xi.y);
    atomicAdd(du + 2, v * xi.z);
    atomicAdd(du + 3, v * xi.w);

    // item <- user direction
    float4 xu = *reinterpret_cast<const float4*>(&g_xw_user[r * DIM + g * 4]);
    float* di = &out_item[c * DIM + g * 4];
    atomicAdd(di + 0, v * xu.x);
    atomicAdd(di + 1, v * xu.y);
    atomicAdd(di + 2, v * xu.z);
    atomicAdd(di + 3, v * xu.w);
}

// ---------------------------------------------------------------------------
// ReLU epilogue over the whole output.
// ---------------------------------------------------------------------------
__global__ void relu_kernel(float4* __restrict__ out, int n4) {
    int i = blockIdx.x * blockDim.x + threadIdx.x;
    if (i < n4) {
        float4 v = out[i];
        v.x = fmaxf(v.x, 0.f);
        v.y = fmaxf(v.y, 0.f);
        v.z = fmaxf(v.z, 0.f);
        v.w = fmaxf(v.w, 0.f);
        out[i] = v;
    }
}

extern "C" void kernel_launch(void* const* d_in, const int* in_sizes, int n_in,
                              void* d_out, int out_size) {
    const float* user_x      = (const float*)d_in[0];
    const float* item_x      = (const float*)d_in[1];
    const float* user_weight = (const float*)d_in[2];
    const float* item_weight = (const float*)d_in[3];
    const int*   ui_rows     = (const int*)d_in[4];
    const int*   ui_cols     = (const int*)d_in[5];
    const float* ui_vals     = (const float*)d_in[6];

    float* out_user = (float*)d_out;
    float* out_item = out_user + (size_t)N_USERS * DIM;

    float* xw_user_p;
    float* xw_item_p;
    cudaGetSymbolAddress((void**)&xw_user_p, g_xw_user);
    cudaGetSymbolAddress((void**)&xw_item_p, g_xw_item);

    // 1) zero the output (it is poisoned to 0xAA before timing)
    int n4 = (N_USERS + N_ITEMS) * DIM / 4;
    zero_kernel<<<(n4 + 255) / 256, 256>>>((float4*)d_out, n4);

    // 2) dense projections
    gemm64_kernel<<<(N_USERS + 3) / 4, 256>>>(user_x, user_weight, xw_user_p, N_USERS);
    gemm64_kernel<<<(N_ITEMS + 3) / 4, 256>>>(item_x, item_weight, xw_item_p, N_ITEMS);

    // 3) fused bidirectional scatter-add
    long long nthreads = (long long)NNZ * 16;
    int nblocks = (int)((nthreads + 255) / 256);
    scatter_kernel<<<nblocks, 256>>>(ui_rows, ui_cols, ui_vals, out_user, out_item);

    // 4) ReLU
    relu_kernel<<<(n4 + 255) / 256, 256>>>((float4*)d_out, n4);
}

// round 8
// speedup vs baseline: 2.2894x; 2.2894x over previous
#include <cuda_runtime.h>

#define N_USERS 100000
#define N_ITEMS 50000
#define NNZ     1600000
#define DIM     64

// Scratch for the projected features (device globals: no allocation allowed).
__device__ float g_xw_user[N_USERS * DIM];
__device__ float g_xw_item[N_ITEMS * DIM];

// ---------------------------------------------------------------------------
// Vectorized global reduction: one 16B red.global.add.v4.f32 (sm_90+).
// ---------------------------------------------------------------------------
__device__ __forceinline__ void red_add_v4(float* p, float4 v) {
    asm volatile("red.global.add.v4.f32 [%0], {%1, %2, %3, %4};"
                 :: "l"(p), "f"(v.x), "f"(v.y), "f"(v.z), "f"(v.w)
                 : "memory");
}

// ---------------------------------------------------------------------------
// Dense projection: out[m, :] = x[m, :] @ W   (W is DIM x DIM, row-major)
// 256 threads/block = 16 rows x 16 float4-cols. W staged in shared as float4.
// ---------------------------------------------------------------------------
__global__ void gemm64_kernel(const float* __restrict__ x,
                              const float* __restrict__ W,
                              float* __restrict__ out, int M) {
    __shared__ float4 sW[DIM * 16];           // 64 rows x 16 float4 cols
    int tid = threadIdx.x;
    #pragma unroll
    for (int i = 0; i < 4; i++)
        sW[tid + i * 256] = reinterpret_cast<const float4*>(W)[tid + i * 256];
    __syncthreads();

    int row = blockIdx.x * 16 + (tid >> 4);
    int c4  = tid & 15;
    if (row >= M) return;

    const float* xr = x + row * DIM;
    float4 acc = make_float4(0.f, 0.f, 0.f, 0.f);
    #pragma unroll
    for (int k = 0; k < DIM; k++) {
        float  xv = xr[k];                    // broadcast across 16 threads
        float4 w  = sW[k * 16 + c4];
        acc.x = fmaf(xv, w.x, acc.x);
        acc.y = fmaf(xv, w.y, acc.y);
        acc.z = fmaf(xv, w.z, acc.z);
        acc.w = fmaf(xv, w.w, acc.w);
    }
    reinterpret_cast<float4*>(out)[row * 16 + c4] = acc;
}

// ---------------------------------------------------------------------------
// Zero-fill the (poisoned) output buffer.
// ---------------------------------------------------------------------------
__global__ void zero_kernel(float4* __restrict__ out, int n4) {
    int i = blockIdx.x * blockDim.x + threadIdx.x;
    if (i < n4) out[i] = make_float4(0.f, 0.f, 0.f, 0.f);
}

// ---------------------------------------------------------------------------
// Fused bidirectional scatter:
//   out_user[r] += v * xw_item[c]     (ui_graph @ xw_item)
//   out_item[c] += v * xw_user[r]     (ui_graph^T @ xw_user)
// 16 threads per edge; thread g handles dims [4g, 4g+4) via one red.v4 each way.
// ---------------------------------------------------------------------------
__global__ void scatter_kernel(const int*   __restrict__ rows,
                               const int*   __restrict__ cols,
                               const float* __restrict__ vals,
                               float* __restrict__ out_user,
                               float* __restrict__ out_item) {
    long long t = (long long)blockIdx.x * blockDim.x + threadIdx.x;
    int e = (int)(t >> 4);
    int g = (int)(t & 15);
    if (e >= NNZ) return;

    int   r = rows[e];
    int   c = cols[e];
    float v = vals[e];

    // user <- item direction
    float4 xi = *reinterpret_cast<const float4*>(&g_xw_item[c * DIM + g * 4]);
    // item <- user direction
    float4 xu = *reinterpret_cast<const float4*>(&g_xw_user[r * DIM + g * 4]);

    float4 mu = make_float4(v * xi.x, v * xi.y, v * xi.z, v * xi.w);
    float4 mi = make_float4(v * xu.x, v * xu.y, v * xu.z, v * xu.w);

    red_add_v4(&out_user[r * DIM + g * 4], mu);
    red_add_v4(&out_item[c * DIM + g * 4], mi);
}

// ---------------------------------------------------------------------------
// ReLU epilogue over the whole output.
// ---------------------------------------------------------------------------
__global__ void relu_kernel(float4* __restrict__ out, int n4) {
    int i = blockIdx.x * blockDim.x + threadIdx.x;
    if (i < n4) {
        float4 v = out[i];
        v.x = fmaxf(v.x, 0.f);
        v.y = fmaxf(v.y, 0.f);
        v.z = fmaxf(v.z, 0.f);
        v.w = fmaxf(v.w, 0.f);
        out[i] = v;
    }
}

extern "C" void kernel_launch(void* const* d_in, const int* in_sizes, int n_in,
                              void* d_out, int out_size) {
    const float* user_x      = (const float*)d_in[0];
    const float* item_x      = (const float*)d_in[1];
    const float* user_weight = (const float*)d_in[2];
    const float* item_weight = (const float*)d_in[3];
    const int*   ui_rows     = (const int*)d_in[4];
    const int*   ui_cols     = (const int*)d_in[5];
    const float* ui_vals     = (const float*)d_in[6];

    float* out_user = (float*)d_out;
    float* out_item = out_user + (size_t)N_USERS * DIM;

    float* xw_user_p;
    float* xw_item_p;
    cudaGetSymbolAddress((void**)&xw_user_p, g_xw_user);
    cudaGetSymbolAddress((void**)&xw_item_p, g_xw_item);

    // 1) zero the output (it is poisoned to 0xAA before timing)
    int n4 = (N_USERS + N_ITEMS) * DIM / 4;
    zero_kernel<<<(n4 + 255) / 256, 256>>>((float4*)d_out, n4);

    // 2) dense projections
    gemm64_kernel<<<(N_USERS + 15) / 16, 256>>>(user_x, user_weight, xw_user_p, N_USERS);
    gemm64_kernel<<<(N_ITEMS + 15) / 16, 256>>>(item_x, item_weight, xw_item_p, N_ITEMS);

    // 3) fused bidirectional scatter-add (vectorized reductions)
    long long nthreads = (long long)NNZ * 16;
    int nblocks = (int)((nthreads + 255) / 256);
    scatter_kernel<<<nblocks, 256>>>(ui_rows, ui_cols, ui_vals, out_user, out_item);

    // 4) ReLU
    relu_kernel<<<(n4 + 255) / 256, 256>>>((float4*)d_out, n4);
}

// round 9
// speedup vs baseline: 2.4334x; 1.0629x over previous
#include <cuda_runtime.h>

#define N_USERS 100000
#define N_ITEMS 50000
#define NNZ     1600000
#define DIM     64

// Scratch for the projected features (device globals: no allocation allowed).
__device__ float g_xw_user[N_USERS * DIM];
__device__ float g_xw_item[N_ITEMS * DIM];

// ---------------------------------------------------------------------------
// Vectorized global reduction: one 16B red.global.add.v4.f32 (sm_90+).
// ---------------------------------------------------------------------------
__device__ __forceinline__ void red_add_v4(float* p, float4 v) {
    asm volatile("red.global.add.v4.f32 [%0], {%1, %2, %3, %4};"
                 :: "l"(p), "f"(v.x), "f"(v.y), "f"(v.z), "f"(v.w)
                 : "memory");
}

// ---------------------------------------------------------------------------
// Dense projection: out[m, :] = x[m, :] @ W   (W is DIM x DIM, row-major)
// 256 threads/block = 16 rows x 16 float4-cols. W staged in shared as float4.
// x row loaded via 16 x LDG.128 (was 64 x LDG.32).
// ---------------------------------------------------------------------------
__global__ __launch_bounds__(256) void gemm64_kernel(
        const float* __restrict__ x,
        const float* __restrict__ W,
        float* __restrict__ out, int M) {
    __shared__ float4 sW[DIM * 16];           // 64 rows x 16 float4 cols
    int tid = threadIdx.x;
    #pragma unroll
    for (int i = 0; i < 4; i++)
        sW[tid + i * 256] = reinterpret_cast<const float4*>(W)[tid + i * 256];
    __syncthreads();

    int row = blockIdx.x * 16 + (tid >> 4);
    int c4  = tid & 15;
    if (row >= M) return;

    const float4* xr4 = reinterpret_cast<const float4*>(x + row * DIM);
    float4 acc = make_float4(0.f, 0.f, 0.f, 0.f);
    #pragma unroll
    for (int k4 = 0; k4 < 16; k4++) {
        float4 xv = xr4[k4];                  // vector load, broadcast across 16 threads
        {
            float4 w = sW[(k4 * 4 + 0) * 16 + c4];
            acc.x = fmaf(xv.x, w.x, acc.x); acc.y = fmaf(xv.x, w.y, acc.y);
            acc.z = fmaf(xv.x, w.z, acc.z); acc.w = fmaf(xv.x, w.w, acc.w);
        }
        {
            float4 w = sW[(k4 * 4 + 1) * 16 + c4];
            acc.x = fmaf(xv.y, w.x, acc.x); acc.y = fmaf(xv.y, w.y, acc.y);
            acc.z = fmaf(xv.y, w.z, acc.z); acc.w = fmaf(xv.y, w.w, acc.w);
        }
        {
            float4 w = sW[(k4 * 4 + 2) * 16 + c4];
            acc.x = fmaf(xv.z, w.x, acc.x); acc.y = fmaf(xv.z, w.y, acc.y);
            acc.z = fmaf(xv.z, w.z, acc.z); acc.w = fmaf(xv.z, w.w, acc.w);
        }
        {
            float4 w = sW[(k4 * 4 + 3) * 16 + c4];
            acc.x = fmaf(xv.w, w.x, acc.x); acc.y = fmaf(xv.w, w.y, acc.y);
            acc.z = fmaf(xv.w, w.z, acc.z); acc.w = fmaf(xv.w, w.w, acc.w);
        }
    }
    reinterpret_cast<float4*>(out)[row * 16 + c4] = acc;
}

// ---------------------------------------------------------------------------
// Zero-fill the (poisoned) output buffer.
// ---------------------------------------------------------------------------
__global__ void zero_kernel(float4* __restrict__ out, int n4) {
    int i = blockIdx.x * blockDim.x + threadIdx.x;
    if (i < n4) out[i] = make_float4(0.f, 0.f, 0.f, 0.f);
}

// ---------------------------------------------------------------------------
// Fused bidirectional scatter (UNCHANGED from the 140.8us measured version):
//   out_user[r] += v * xw_item[c]     (ui_graph @ xw_item)
//   out_item[c] += v * xw_user[r]     (ui_graph^T @ xw_user)
// 16 threads per edge; thread g handles dims [4g, 4g+4) via one red.v4 each way.
// ---------------------------------------------------------------------------
__global__ void scatter_kernel(const int*   __restrict__ rows,
                               const int*   __restrict__ cols,
                               const float* __restrict__ vals,
                               float* __restrict__ out_user,
                               float* __restrict__ out_item) {
    long long t = (long long)blockIdx.x * blockDim.x + threadIdx.x;
    int e = (int)(t >> 4);
    int g = (int)(t & 15);
    if (e >= NNZ) return;

    int   r = rows[e];
    int   c = cols[e];
    float v = vals[e];

    float4 xi = *reinterpret_cast<const float4*>(&g_xw_item[c * DIM + g * 4]);
    float4 xu = *reinterpret_cast<const float4*>(&g_xw_user[r * DIM + g * 4]);

    float4 mu = make_float4(v * xi.x, v * xi.y, v * xi.z, v * xi.w);
    float4 mi = make_float4(v * xu.x, v * xu.y, v * xu.z, v * xu.w);

    red_add_v4(&out_user[r * DIM + g * 4], mu);
    red_add_v4(&out_item[c * DIM + g * 4], mi);
}

// ---------------------------------------------------------------------------
// ReLU epilogue over the whole output.
// ---------------------------------------------------------------------------
__global__ void relu_kernel(float4* __restrict__ out, int n4) {
    int i = blockIdx.x * blockDim.x + threadIdx.x;
    if (i < n4) {
        float4 v = out[i];
        v.x = fmaxf(v.x, 0.f);
        v.y = fmaxf(v.y, 0.f);
        v.z = fmaxf(v.z, 0.f);
        v.w = fmaxf(v.w, 0.f);
        out[i] = v;
    }
}

extern "C" void kernel_launch(void* const* d_in, const int* in_sizes, int n_in,
                              void* d_out, int out_size) {
    const float* user_x      = (const float*)d_in[0];
    const float* item_x      = (const float*)d_in[1];
    const float* user_weight = (const float*)d_in[2];
    const float* item_weight = (const float*)d_in[3];
    const int*   ui_rows     = (const int*)d_in[4];
    const int*   ui_cols     = (const int*)d_in[5];
    const float* ui_vals     = (const float*)d_in[6];

    float* out_user = (float*)d_out;
    float* out_item = out_user + (size_t)N_USERS * DIM;

    float* xw_user_p;
    float* xw_item_p;
    cudaGetSymbolAddress((void**)&xw_user_p, g_xw_user);
    cudaGetSymbolAddress((void**)&xw_item_p, g_xw_item);

    // 1) zero the output (it is poisoned to 0xAA before timing)
    int n4 = (N_USERS + N_ITEMS) * DIM / 4;
    zero_kernel<<<(n4 + 255) / 256, 256>>>((float4*)d_out, n4);

    // 2) dense projections
    gemm64_kernel<<<(N_USERS + 15) / 16, 256>>>(user_x, user_weight, xw_user_p, N_USERS);
    gemm64_kernel<<<(N_ITEMS + 15) / 16, 256>>>(item_x, item_weight, xw_item_p, N_ITEMS);

    // 3) fused bidirectional scatter-add (vectorized reductions)
    long long nthreads = (long long)NNZ * 16;
    int nblocks = (int)((nthreads + 255) / 256);
    scatter_kernel<<<nblocks, 256>>>(ui_rows, ui_cols, ui_vals, out_user, out_item);

    // 4) ReLU
    relu_kernel<<<(n4 + 255) / 256, 256>>>((float4*)d_out, n4);
}

// round 13
// speedup vs baseline: 3.0716x; 1.2622x over previous
#include <cuda_runtime.h>

#define N_USERS 100000
#define N_ITEMS 50000
#define NNZ     1600000
#define DIM     64

// Scratch for the projected features (device globals: no allocation allowed).
__device__ float g_xw_user[N_USERS * DIM];
__device__ float g_xw_item[N_ITEMS * DIM];

// ---------------------------------------------------------------------------
// Vectorized global reduction: one 16B red.global.add.v4.f32 (sm_90+).
// ---------------------------------------------------------------------------
__device__ __forceinline__ void red_add_v4(float* p, float4 v) {
    asm volatile("red.global.add.v4.f32 [%0], {%1, %2, %3, %4};"
                 :: "l"(p), "f"(v.x), "f"(v.y), "f"(v.z), "f"(v.w)
                 : "memory");
}

__device__ __forceinline__ void fma4(float4& acc, float s, float4 w) {
    acc.x = fmaf(s, w.x, acc.x);
    acc.y = fmaf(s, w.y, acc.y);
    acc.z = fmaf(s, w.z, acc.z);
    acc.w = fmaf(s, w.w, acc.w);
}

// ---------------------------------------------------------------------------
// Dense projection with 4x4 register tiling + fused zero of an output slice.
// Block: 256 threads covering 64 rows x 64 cols (16 row-groups x 16 col-groups,
// each thread computes a 4-row x 4-col tile). Per k-step one shared W float4
// feeds 4 rows -> 4x less LDS traffic per output than the 1x4 version.
// ---------------------------------------------------------------------------
__global__ __launch_bounds__(256) void gemm64_tiled_kernel(
        const float* __restrict__ x,
        const float* __restrict__ W,
        float* __restrict__ out, int M,
        float4* __restrict__ zero_dst, int zero_n4) {
    __shared__ float4 sW[DIM * 16];           // 64 k-rows x 16 float4 col-groups
    int tid = threadIdx.x;

    // Fused zero of the (poisoned) final-output slice; overlaps with FMA work.
    {
        int gt = blockIdx.x * 256 + tid;
        int stride = gridDim.x * 256;
        const float4 z = make_float4(0.f, 0.f, 0.f, 0.f);
        for (int i = gt; i < zero_n4; i += stride) zero_dst[i] = z;
    }

    #pragma unroll
    for (int i = 0; i < 4; i++)
        sW[tid + i * 256] = reinterpret_cast<const float4*>(W)[tid + i * 256];
    __syncthreads();

    int rg  = tid >> 4;                       // 0..15 row-group
    int c4  = tid & 15;                       // 0..15 col-group (4 cols)
    int row0 = blockIdx.x * 64 + rg * 4;

    const float4* xr0 = reinterpret_cast<const float4*>(x + (size_t)row0 * DIM);
    bool v0 = (row0 + 0) < M, v1 = (row0 + 1) < M,
         v2 = (row0 + 2) < M, v3 = (row0 + 3) < M;

    float4 a0 = make_float4(0,0,0,0), a1 = a0, a2 = a0, a3 = a0;

    #pragma unroll
    for (int k4 = 0; k4 < 16; k4++) {
        float4 x0 = v0 ? xr0[k4]          : make_float4(0,0,0,0);
        float4 x1 = v1 ? xr0[16 + k4]     : make_float4(0,0,0,0);
        float4 x2 = v2 ? xr0[32 + k4]     : make_float4(0,0,0,0);
        float4 x3 = v3 ? xr0[48 + k4]     : make_float4(0,0,0,0);

        float4 w0 = sW[(k4 * 4 + 0) * 16 + c4];
        fma4(a0, x0.x, w0); fma4(a1, x1.x, w0); fma4(a2, x2.x, w0); fma4(a3, x3.x, w0);
        float4 w1 = sW[(k4 * 4 + 1) * 16 + c4];
        fma4(a0, x0.y, w1); fma4(a1, x1.y, w1); fma4(a2, x2.y, w1); fma4(a3, x3.y, w1);
        float4 w2 = sW[(k4 * 4 + 2) * 16 + c4];
        fma4(a0, x0.z, w2); fma4(a1, x1.z, w2); fma4(a2, x2.z, w2); fma4(a3, x3.z, w2);
        float4 w3 = sW[(k4 * 4 + 3) * 16 + c4];
        fma4(a0, x0.w, w3); fma4(a1, x1.w, w3); fma4(a2, x2.w, w3); fma4(a3, x3.w, w3);
    }

    float4* o4 = reinterpret_cast<float4*>(out) + (size_t)row0 * 16 + c4;
    if (v0) o4[0]  = a0;
    if (v1) o4[16] = a1;
    if (v2) o4[32] = a2;
    if (v3) o4[48] = a3;
}

// ---------------------------------------------------------------------------
// Fused bidirectional scatter (UNCHANGED from the 141us measured version):
//   out_user[r] += v * xw_item[c]     (ui_graph @ xw_item)
//   out_item[c] += v * xw_user[r]     (ui_graph^T @ xw_user)
// 16 threads per edge; thread g handles dims [4g, 4g+4) via one red.v4 each way.
// ---------------------------------------------------------------------------
__global__ void scatter_kernel(const int*   __restrict__ rows,
                               const int*   __restrict__ cols,
                               const float* __restrict__ vals,
                               float* __restrict__ out_user,
                               float* __restrict__ out_item) {
    long long t = (long long)blockIdx.x * blockDim.x + threadIdx.x;
    int e = (int)(t >> 4);
    int g = (int)(t & 15);
    if (e >= NNZ) return;

    int   r = rows[e];
    int   c = cols[e];
    float v = vals[e];

    float4 xi = *reinterpret_cast<const float4*>(&g_xw_item[c * DIM + g * 4]);
    float4 xu = *reinterpret_cast<const float4*>(&g_xw_user[r * DIM + g * 4]);

    float4 mu = make_float4(v * xi.x, v * xi.y, v * xi.z, v * xi.w);
    float4 mi = make_float4(v * xu.x, v * xu.y, v * xu.z, v * xu.w);

    red_add_v4(&out_user[r * DIM + g * 4], mu);
    red_add_v4(&out_item[c * DIM + g * 4], mi);
}

// ---------------------------------------------------------------------------
// ReLU epilogue over the whole output.
// ---------------------------------------------------------------------------
__global__ void relu_kernel(float4* __restrict__ out, int n4) {
    int i = blockIdx.x * blockDim.x + threadIdx.x;
    if (i < n4) {
        float4 v = out[i];
        v.x = fmaxf(v.x, 0.f);
        v.y = fmaxf(v.y, 0.f);
        v.z = fmaxf(v.z, 0.f);
        v.w = fmaxf(v.w, 0.f);
        out[i] = v;
    }
}

extern "C" void kernel_launch(void* const* d_in, const int* in_sizes, int n_in,
                              void* d_out, int out_size) {
    const float* user_x      = (const float*)d_in[0];
    const float* item_x      = (const float*)d_in[1];
    const float* user_weight = (const float*)d_in[2];
    const float* item_weight = (const float*)d_in[3];
    const int*   ui_rows     = (const int*)d_in[4];
    const int*   ui_cols     = (const int*)d_in[5];
    const float* ui_vals     = (const float*)d_in[6];

    float* out_user = (float*)d_out;
    float* out_item = out_user + (size_t)N_USERS * DIM;

    float* xw_user_p;
    float* xw_item_p;
    cudaGetSymbolAddress((void**)&xw_user_p, g_xw_user);
    cudaGetSymbolAddress((void**)&xw_item_p, g_xw_item);

    // 1+2) dense projections, each also zeroing its half of the poisoned output
    int user_n4 = N_USERS * DIM / 4;
    int item_n4 = N_ITEMS * DIM / 4;
    gemm64_tiled_kernel<<<(N_USERS + 63) / 64, 256>>>(
        user_x, user_weight, xw_user_p, N_USERS, (float4*)out_user, user_n4);
    gemm64_tiled_kernel<<<(N_ITEMS + 63) / 64, 256>>>(
        item_x, item_weight, xw_item_p, N_ITEMS, (float4*)out_item, item_n4);

    // 3) fused bidirectional scatter-add (vectorized reductions)
    long long nthreads = (long long)NNZ * 16;
    int nblocks = (int)((nthreads + 255) / 256);
    scatter_kernel<<<nblocks, 256>>>(ui_rows, ui_cols, ui_vals, out_user, out_item);

    // 4) ReLU
    int n4 = user_n4 + item_n4;
    relu_kernel<<<(n4 + 255) / 256, 256>>>((float4*)d_out, n4);
}